// round 3
// baseline (speedup 1.0000x reference)
#include <cuda_runtime.h>

#define BB 2048
#define TT 1024
#define DD 64
#define HH 16
#define INV_TAU (1.0f/6.0f)

typedef unsigned long long u64;

__device__ __forceinline__ u64 pk2(float lo, float hi) {
    u64 r; asm("mov.b64 %0, {%1,%2};" : "=l"(r) : "f"(lo), "f"(hi)); return r;
}
__device__ __forceinline__ u64 mul2(u64 a, u64 b) {
    u64 r; asm("mul.rn.f32x2 %0, %1, %2;" : "=l"(r) : "l"(a), "l"(b)); return r;
}
__device__ __forceinline__ u64 fma2(u64 a, u64 b, u64 c) {
    u64 r; asm("fma.rn.f32x2 %0, %1, %2, %3;" : "=l"(r) : "l"(a), "l"(b), "l"(c)); return r;
}
__device__ __forceinline__ float hadd2(u64 a) {
    float lo, hi; asm("mov.b64 {%0,%1}, %2;" : "=f"(lo), "=f"(hi) : "l"(a)); return lo + hi;
}

// One warp per batch. Lane owns d = {2*lane, 2*lane+1}.
// Fuses: synaptic-depression scan -> x_cat write -> input projection (f32x2 GEMM +
// multi-value butterfly reduce) -> sequential ReLU RNN -> hidden + linear output.
__global__ void __launch_bounds__(32) stprnn_fused(
    const float* __restrict__ inputs,   // [B,T,64]
    const float* __restrict__ syn_x0,   // [B,64]
    const float* __restrict__ h0,       // [B,16]
    const float* __restrict__ w_ih,     // [128,16]
    const float* __restrict__ w_hh,     // [16,16]
    const float* __restrict__ bias,     // [16]
    const float* __restrict__ lin_w,    // [16]
    const float* __restrict__ lin_b,    // [1]
    float* __restrict__ out_output,     // [B,T]
    float* __restrict__ out_hidden,     // [B,T,16]
    float* __restrict__ out_xcat)       // [B,T,128]
{
    const int lane = threadIdx.x;
    const int b    = blockIdx.x;
    // After the butterfly reduce, this lane holds xw[j], j = bitrev4(lane&15).
    const int j = ((lane & 1) << 3) | ((lane & 2) << 1) | ((lane & 4) >> 1) | ((lane & 8) >> 3);

    // ---- register-stationary weights ----
    u64 wA[HH], wB[HH];                  // wA[h] = (W[2l][h], W[2l+1][h]); wB: rows 64+2l, 65+2l
#pragma unroll
    for (int h = 0; h < HH; h++) {
        wA[h] = pk2(w_ih[(2*lane    )*HH + h], w_ih[(2*lane + 1)*HH + h]);
        wB[h] = pk2(w_ih[(64+2*lane)*HH + h], w_ih[(65+2*lane)*HH + h]);
    }
    float whh[HH];
#pragma unroll
    for (int i = 0; i < HH; i++) whh[i] = w_hh[i*HH + j];
    const float biasj = bias[j];
    const float lwj   = lin_w[j];
    const float lb    = lin_b[0];

    // ---- states ----
    float2 s;
    s.x = syn_x0[b*DD + 2*lane];
    s.y = syn_x0[b*DD + 2*lane + 1];
    float hj = h0[b*HH + j];             // lane holds h[j]; lanes 16-31 mirror

    // ---- pointers ----
    const float2* ip = reinterpret_cast<const float2*>(inputs) + (size_t)b*TT*(DD/2) + lane;
    float2*       xc = reinterpret_cast<float2*>(out_xcat)     + (size_t)b*TT*64     + lane;
    float*       hid = out_hidden + (size_t)b*TT*HH;
    float*        op = out_output + (size_t)b*TT;

    // ---- input prefetch ring (depth 4 to cover DRAM latency) ----
    float2 buf[4];
#pragma unroll
    for (int p = 0; p < 4; p++) buf[p] = ip[p*(DD/2)];

    for (int t = 0; t < TT; t++) {
        float2 in = buf[t & 3];
        if (t + 4 < TT) buf[t & 3] = ip[(t + 4)*(DD/2)];

        // ---- synaptic depression: s' = r + e*(s - r), r = INV_TAU/k, e = exp(-k)
        float kx = fmaf(0.5f, in.x, INV_TAU);
        float ky = fmaf(0.5f, in.y, INV_TAU);
        float ex = __expf(-kx);
        float ey = __expf(-ky);
        float rx = __fdividef(INV_TAU, kx);
        float ry = __fdividef(INV_TAU, ky);

        float2 sx;                        // syn (pre-update) * input
        sx.x = s.x * in.x;
        sx.y = s.y * in.y;

        // ---- x_cat output (coalesced 256B stores per warp)
        xc[t*64]      = in;
        xc[t*64 + 32] = sx;

        // state update AFTER emission
        s.x = fmaf(ex, s.x - rx, rx);
        s.y = fmaf(ey, s.y - ry, ry);

        // ---- input projection partials: p[h] = sum over this lane's 2 d's
        u64 inP = pk2(in.x, in.y);
        u64 sxP = pk2(sx.x, sx.y);
        float p16[16];
#pragma unroll
        for (int h = 0; h < HH; h++) {
            u64 a = mul2(inP, wA[h]);
            a = fma2(sxP, wB[h], a);
            p16[h] = hadd2(a);
        }

        // ---- multi-value butterfly reduce over lanes; lane ends with xw[bitrev4(lane)]
        float p8[8];
#pragma unroll
        for (int i = 0; i < 8; i++) {
            bool lo = (lane & 1) == 0;
            float send = lo ? p16[8 + i] : p16[i];
            float recv = __shfl_xor_sync(0xffffffffu, send, 1);
            p8[i] = (lo ? p16[i] : p16[8 + i]) + recv;
        }
        float p4[4];
#pragma unroll
        for (int i = 0; i < 4; i++) {
            bool lo = (lane & 2) == 0;
            float send = lo ? p8[4 + i] : p8[i];
            float recv = __shfl_xor_sync(0xffffffffu, send, 2);
            p4[i] = (lo ? p8[i] : p8[4 + i]) + recv;
        }
        float p2[2];
#pragma unroll
        for (int i = 0; i < 2; i++) {
            bool lo = (lane & 4) == 0;
            float send = lo ? p4[2 + i] : p4[i];
            float recv = __shfl_xor_sync(0xffffffffu, send, 4);
            p2[i] = (lo ? p4[i] : p4[2 + i]) + recv;
        }
        float xwv;
        {
            bool lo = (lane & 8) == 0;
            float send = lo ? p2[1] : p2[0];
            float recv = __shfl_xor_sync(0xffffffffu, send, 8);
            xwv = (lo ? p2[0] : p2[1]) + recv;
            xwv += __shfl_xor_sync(0xffffffffu, xwv, 16);
        }

        // ---- RNN step: h_new[j] = relu(xw[j] + bias[j] + sum_i h[i]*Whh[i][j])
        float acc = xwv + biasj;
#pragma unroll
        for (int i = 0; i < HH; i++) {
            // lane holding h[i] is bitrev4(i) (lanes 0-15)
            const int src = ((i & 1) << 3) | ((i & 2) << 1) | ((i & 4) >> 1) | ((i & 8) >> 3);
            float hi_ = __shfl_sync(0xffffffffu, hj, src);
            acc = fmaf(hi_, whh[i], acc);
        }
        hj = fmaxf(acc, 0.0f);

        if (lane < HH) hid[t*HH + j] = hj;

        // ---- output: dot(h, lin_w) + lin_b (reduce over lanes 0..15)
        float v = (lane < HH) ? hj * lwj : 0.0f;
        v += __shfl_xor_sync(0xffffffffu, v, 8);
        v += __shfl_xor_sync(0xffffffffu, v, 4);
        v += __shfl_xor_sync(0xffffffffu, v, 2);
        v += __shfl_xor_sync(0xffffffffu, v, 1);
        if (lane == 0) op[t] = v + lb;
    }
}

extern "C" void kernel_launch(void* const* d_in, const int* in_sizes, int n_in,
                              void* d_out, int out_size) {
    const float* inputs = (const float*)d_in[0];   // [B,T,64]
    const float* syn_x0 = (const float*)d_in[1];   // [B,64]
    const float* h0     = (const float*)d_in[2];   // [B,16]
    const float* w_ih   = (const float*)d_in[3];   // [128,16]
    const float* w_hh   = (const float*)d_in[4];   // [16,16]
    const float* bias   = (const float*)d_in[5];   // [16]
    const float* lin_w  = (const float*)d_in[6];   // [16,1]
    const float* lin_b  = (const float*)d_in[7];   // [1]

    float* out = (float*)d_out;
    // tuple concat order: output [B,T,1], hidden [B,T,16], x_cat [B,T,128]
    float* out_output = out;
    float* out_hidden = out + (size_t)BB*TT;
    float* out_xcat   = out + (size_t)BB*TT + (size_t)BB*TT*HH;

    stprnn_fused<<<BB, 32>>>(inputs, syn_x0, h0, w_ih, w_hh, bias, lin_w, lin_b,
                             out_output, out_hidden, out_xcat);
}